// round 15
// baseline (speedup 1.0000x reference)
#include <cuda_runtime.h>
#include <cuda_fp16.h>
#include <cstdint>

// Problem constants
#define BB   2
#define TT   8192
#define DD   512
#define HH   8
#define WW   256
#define DH   64
#define NC   32

// ---------------------------------------------------------------------------
// Static device scratch (single rn-fp16 representations; err ~2^-12)
// ---------------------------------------------------------------------------
__device__ __half g_xh[(size_t)BB * TT * DD];
__device__ __half g_Wh[4 * DD * DD];                // q,k,v,o stacked
__device__ __half g_Qh[(size_t)BB * HH * TT * DH];
__device__ __half g_Kh[(size_t)BB * HH * TT * DH];
__device__ __half g_Vh[(size_t)BB * HH * TT * DH];
__device__ __half g_Oh[(size_t)BB * TT * DD];

// ---------------------------------------------------------------------------
// Helpers (base sm_103 features only: mma.sync / ldmatrix / cp.async)
// ---------------------------------------------------------------------------
__device__ __forceinline__ uint32_t smem_to_u32(const void* p) {
    uint32_t a;
    asm("{ .reg .u64 t; cvta.to.shared.u64 t, %1; cvt.u32.u64 %0, t; }"
        : "=r"(a) : "l"(p));
    return a;
}

#define SWZ128(b) ((b) ^ (((b) >> 3) & 0x70))

__device__ __forceinline__ void cp16(uint32_t dst, const void* src) {
    asm volatile("cp.async.cg.shared.global [%0], [%1], 16;" :: "r"(dst), "l"(src) : "memory");
}
#define CP_COMMIT() asm volatile("cp.async.commit_group;" ::: "memory")
#define CP_WAIT(N)  asm volatile("cp.async.wait_group %0;" :: "n"(N) : "memory")

#define LDSM_X4(R, ADDR) \
    asm volatile("ldmatrix.sync.aligned.m8n8.x4.shared.b16 {%0,%1,%2,%3}, [%4];" \
        : "=r"((R)[0]), "=r"((R)[1]), "=r"((R)[2]), "=r"((R)[3]) : "r"(ADDR))

#define LDSM_X4T(R, ADDR) \
    asm volatile("ldmatrix.sync.aligned.m8n8.x4.trans.shared.b16 {%0,%1,%2,%3}, [%4];" \
        : "=r"((R)[0]), "=r"((R)[1]), "=r"((R)[2]), "=r"((R)[3]) : "r"(ADDR))

__device__ __forceinline__ void mma_f16(float c[4], const uint32_t a[4],
                                        uint32_t b0, uint32_t b1) {
    asm volatile(
        "mma.sync.aligned.m16n8k16.row.col.f32.f16.f16.f32 "
        "{%0,%1,%2,%3}, {%4,%5,%6,%7}, {%8,%9}, {%0,%1,%2,%3};"
        : "+f"(c[0]), "+f"(c[1]), "+f"(c[2]), "+f"(c[3])
        : "r"(a[0]), "r"(a[1]), "r"(a[2]), "r"(a[3]), "r"(b0), "r"(b1));
}

__device__ __forceinline__ uint32_t pack_h2(float a, float b) {
    __half2 h = __floats2half2_rn(a, b);
    return *reinterpret_cast<uint32_t*>(&h);
}

// ---------------------------------------------------------------------------
// Input prep, sliced for pipelining:
//   convert_w : 4 weight matrices only (small, gates all chains)
//   convert_x : one contiguous row-slice of x (per chain, in-stream)
// ---------------------------------------------------------------------------
#define NW4 ((DD * DD) / 4)

__global__ void __launch_bounds__(256) convert_w(
    const float4* __restrict__ wq, const float4* __restrict__ wk,
    const float4* __restrict__ wv, const float4* __restrict__ wo)
{
    int j = blockIdx.x * 256 + threadIdx.x;
    if (j >= 4 * NW4) return;
    int w = j >> 16;            // NW4 = 65536
    int r = j & (NW4 - 1);
    const float4* ws[4] = { wq, wk, wv, wo };
    float4 a = ws[w][r];
    uint32_t* dst = (uint32_t*)g_Wh + 2 * (w * NW4 + r);
    dst[0] = pack_h2(a.x, a.y);
    dst[1] = pack_h2(a.z, a.w);
}

__global__ void __launch_bounds__(256) convert_x(
    const float4* __restrict__ x, int f4_off, int n4)
{
    int i = blockIdx.x * 256 + threadIdx.x;
    if (i >= n4) return;
    float4 a = x[f4_off + i];
    uint32_t* dst = (uint32_t*)g_xh + 2 * (f4_off + i);
    dst[0] = pack_h2(a.x, a.y);
    dst[1] = pack_h2(a.z, a.w);
}

// ---------------------------------------------------------------------------
// Fused QKV GEMM (R12 shape), m-sliced via m_off (absolute 128-row tiles).
// A fragments register-resident across z; ratio 3.0 MMA/LDSM.
// Stage = A 16K + 3 x B 8K = 40K, double buffered 80K -> 2 CTAs/SM.
// ---------------------------------------------------------------------------
__global__ void __launch_bounds__(256, 2) qkv_gemm(
    const __half* __restrict__ A, const __half* __restrict__ WB,
    const float* __restrict__ bq, const float* __restrict__ bk,
    const float* __restrict__ bv,
    __half* __restrict__ outQ, __half* __restrict__ outK,
    __half* __restrict__ outV, int m_off)
{
    constexpr int STG = 40960;
    extern __shared__ char smc[];
    const uint32_t su = smem_to_u32(smc);
    const int tid = threadIdx.x, lane = tid & 31, wid = tid >> 5;
    const int wm = wid & 3, wn = wid >> 2;
    const int bm = m_off + blockIdx.y * 128, bn = blockIdx.x * 64;

    const __half* srcA = A + (size_t)bm * DD;
    const __half* srcB[3] = {
        WB + 0 * (size_t)DD * DD + (size_t)bn * DD,
        WB + 1 * (size_t)DD * DD + (size_t)bn * DD,
        WB + 2 * (size_t)DD * DD + (size_t)bn * DD };

    auto load_stage = [&](int s, int buf) {
        const uint32_t base = su + buf * STG;
        const int k0 = s * 64;
#pragma unroll
        for (int p = 0; p < 10; p++) {
            int idx = p * 256 + tid;
            if (idx >= 2560) break;
            if (idx < 1024) {
                int row = idx >> 3, col = idx & 7;
                cp16(base + SWZ128(row * 128 + col * 16),
                     srcA + (size_t)row * DD + k0 + col * 8);
            } else {
                int j = idx - 1024;
                int z = j >> 9, row = (j >> 3) & 63, col = j & 7;
                cp16(base + 16384 + z * 8192 + SWZ128(row * 128 + col * 16),
                     srcB[z] + (size_t)row * DD + k0 + col * 8);
            }
        }
    };

    float c[3][2][4][4] = {};

    load_stage(0, 0); CP_COMMIT();

    for (int s = 0; s < 8; s++) {
        CP_WAIT(0);
        __syncthreads();
        if (s < 7) { load_stage(s + 1, (s + 1) & 1); CP_COMMIT(); }
        const uint32_t bA = su + (s & 1) * STG;
#pragma unroll
        for (int q = 0; q < 4; q++) {
            uint32_t ah[2][4];
#pragma unroll
            for (int mt = 0; mt < 2; mt++) {
                const int row = wm * 32 + mt * 16 + (lane & 15);
                const uint32_t off = SWZ128(row * 128 + q * 32 + (lane >> 4) * 16);
                LDSM_X4(ah[mt], bA + off);
            }
#pragma unroll
            for (int z = 0; z < 3; z++) {
                const uint32_t bB = bA + 16384 + z * 8192;
#pragma unroll
                for (int nt2 = 0; nt2 < 2; nt2++) {
                    const int n = wn * 32 + nt2 * 16 + (lane & 7) + ((lane >> 4) & 1) * 8;
                    const uint32_t off = SWZ128(n * 128 + q * 32 + ((lane >> 3) & 1) * 16);
                    uint32_t bh[4];
                    LDSM_X4(bh, bB + off);
#pragma unroll
                    for (int mt = 0; mt < 2; mt++) {
                        mma_f16(c[z][mt][2 * nt2],     ah[mt], bh[0], bh[1]);
                        mma_f16(c[z][mt][2 * nt2 + 1], ah[mt], bh[2], bh[3]);
                    }
                }
            }
        }
    }

#pragma unroll
    for (int z = 0; z < 3; z++) {
        const float* bias = (z == 0) ? bq : (z == 1 ? bk : bv);
        __half* dstH = (z == 0) ? outQ : (z == 1 ? outK : outV);
#pragma unroll
        for (int mt = 0; mt < 2; mt++) {
            const int r0 = bm + wm * 32 + mt * 16 + (lane >> 2);
#pragma unroll
            for (int nt = 0; nt < 4; nt++) {
                const int n = bn + wn * 32 + nt * 8 + (lane & 3) * 2;
                const float b0v = bias[n], b1v = bias[n + 1];
                const float v0 = c[z][mt][nt][0] + b0v, v1 = c[z][mt][nt][1] + b1v;
                const float v2 = c[z][mt][nt][2] + b0v, v3 = c[z][mt][nt][3] + b1v;
                const int hh = n >> 6, j = n & 63;
                const int bq_ = r0 >> 13, t = r0 & (TT - 1);
                const size_t off0 = (((size_t)bq_ * HH + hh) * TT + t) * DH + j;
                const size_t off1 = off0 + 8 * DH;
                *(uint32_t*)(dstH + off0) = pack_h2(v0, v1);
                *(uint32_t*)(dstH + off1) = pack_h2(v2, v3);
            }
        }
    }
}

// ---------------------------------------------------------------------------
// Output projection GEMM, m-sliced via m_off.
// ---------------------------------------------------------------------------
__global__ void __launch_bounds__(256, 2) proj_gemm(
    const __half* __restrict__ A, const __half* __restrict__ WB,
    const float* __restrict__ bias, float* __restrict__ outF, int m_off)
{
    constexpr int STG = 24576;
    extern __shared__ char smc[];
    const uint32_t su = smem_to_u32(smc);
    const int tid = threadIdx.x, lane = tid & 31, wid = tid >> 5;
    const int wm = wid & 3, wn = wid >> 2;
    const int bm = m_off + blockIdx.y * 128, bn = blockIdx.x * 64;

    const __half* srcA = A + (size_t)bm * DD;
    const __half* srcB = WB + (size_t)bn * DD;

    auto load_stage = [&](int s, int buf) {
        const uint32_t base = su + buf * STG;
        const int k0 = s * 64;
#pragma unroll
        for (int p = 0; p < 6; p++) {
            int idx = p * 256 + tid;
            if (idx < 1024) {
                int row = idx >> 3, col = idx & 7;
                cp16(base + SWZ128(row * 128 + col * 16),
                     srcA + (size_t)row * DD + k0 + col * 8);
            } else {
                int j = idx - 1024;
                int row = j >> 3, col = j & 7;
                cp16(base + 16384 + SWZ128(row * 128 + col * 16),
                     srcB + (size_t)row * DD + k0 + col * 8);
            }
        }
    };

    float c[2][4][4] = {};

    load_stage(0, 0); CP_COMMIT();

    for (int s = 0; s < 8; s++) {
        CP_WAIT(0);
        __syncthreads();
        if (s < 7) { load_stage(s + 1, (s + 1) & 1); CP_COMMIT(); }
        const uint32_t bA = su + (s & 1) * STG;
        const uint32_t bB = bA + 16384;
#pragma unroll
        for (int q = 0; q < 4; q++) {
            uint32_t ah[2][4];
#pragma unroll
            for (int mt = 0; mt < 2; mt++) {
                const int row = wm * 32 + mt * 16 + (lane & 15);
                const uint32_t off = SWZ128(row * 128 + q * 32 + (lane >> 4) * 16);
                LDSM_X4(ah[mt], bA + off);
            }
#pragma unroll
            for (int nt2 = 0; nt2 < 2; nt2++) {
                const int n = wn * 32 + nt2 * 16 + (lane & 7) + ((lane >> 4) & 1) * 8;
                const uint32_t off = SWZ128(n * 128 + q * 32 + ((lane >> 3) & 1) * 16);
                uint32_t bh[4];
                LDSM_X4(bh, bB + off);
#pragma unroll
                for (int mt = 0; mt < 2; mt++) {
                    mma_f16(c[mt][2 * nt2],     ah[mt], bh[0], bh[1]);
                    mma_f16(c[mt][2 * nt2 + 1], ah[mt], bh[2], bh[3]);
                }
            }
        }
    }

#pragma unroll
    for (int mt = 0; mt < 2; mt++) {
        const int r0 = bm + wm * 32 + mt * 16 + (lane >> 2);
#pragma unroll
        for (int nt = 0; nt < 4; nt++) {
            const int n = bn + wn * 32 + nt * 8 + (lane & 3) * 2;
            const float b0v = bias[n], b1v = bias[n + 1];
            float2 p0; p0.x = c[mt][nt][0] + b0v; p0.y = c[mt][nt][1] + b1v;
            float2 p1; p1.x = c[mt][nt][2] + b0v; p1.y = c[mt][nt][3] + b1v;
            *(float2*)(outF + (size_t)r0 * DD + n) = p0;
            *(float2*)(outF + (size_t)(r0 + 8) * DD + n) = p1;
        }
    }
}

// ---------------------------------------------------------------------------
// Local attention (R11 shape), sliced via bsel + qb_off (32 qb per slice).
// 128 queries/block; 4 warps x 32 query rows; MMA/LDSM = 4.0.
// ---------------------------------------------------------------------------
__global__ void __launch_bounds__(128, 3) attn_mma(int bsel, int qb_off)
{
    extern __shared__ char smc[];
    const uint32_t su = smem_to_u32(smc);
    const int tid = threadIdx.x, lane = tid & 31, wid = tid >> 5;
    const int bid = blockIdx.x;                // [0, 256)
    const int qb = (bid & 31) + qb_off;
    const int h = bid >> 5;
    const int b = bsel;
    const int qstart = qb * 128;
    const int c = qb >> 1;

    const size_t hb = ((size_t)(b * HH + h)) * TT * DH;
    const __half* Qp = g_Qh + hb;
    const __half* Kp = g_Kh + hb;
    const __half* Vp = g_Vh + hb;

    const int k0 = (c == 0) ? 0 : (c - 1) * WW;
    const int k1 = (c == NC - 1) ? TT : (c + 2) * WW;
    const int ntiles = (k1 - k0) >> 6;

    const uint32_t BUF0 = su;
    const uint32_t QSTG = su + 2 * 16384;

    auto load_kv = [&](int i, int buf) {
        const int kt = k0 + i * 64;
        const uint32_t base = BUF0 + buf * 16384;
#pragma unroll
        for (int p = 0; p < 8; p++) {
            int idx = p * 128 + tid;
            int mtx = idx >> 9, row = (idx >> 3) & 63, col = idx & 7;
            cp16(base + mtx * 8192 + SWZ128(row * 128 + col * 16),
                 (mtx ? Vp : Kp) + (size_t)(kt + row) * DH + col * 8);
        }
    };

#pragma unroll
    for (int p = 0; p < 8; p++) {
        int idx = p * 128 + tid;
        int row = idx >> 3, col = idx & 7;
        cp16(QSTG + SWZ128(row * 128 + col * 16),
             Qp + (size_t)(qstart + row) * DH + col * 8);
    }
    load_kv(0, 0);
    CP_COMMIT();

    float o[2][8][4] = {};
    float lsum[2][2] = {};
    uint32_t qh[2][4][4];

    auto compute = [&](uint32_t kb) {
#pragma unroll
        for (int kt2 = 0; kt2 < 4; kt2++) {
            float sfr[2][2][4] = {};
#pragma unroll
            for (int q = 0; q < 4; q++) {
                const int n = kt2 * 16 + (lane & 7) + ((lane >> 4) & 1) * 8;
                const uint32_t off = SWZ128(n * 128 + q * 32 + ((lane >> 3) & 1) * 16);
                uint32_t kh[4];
                LDSM_X4(kh, kb + off);
#pragma unroll
                for (int mf = 0; mf < 2; mf++) {
                    mma_f16(sfr[mf][0], qh[mf][q], kh[0], kh[1]);
                    mma_f16(sfr[mf][1], qh[mf][q], kh[2], kh[3]);
                }
            }

            uint32_t ap[2][4];
#pragma unroll
            for (int mf = 0; mf < 2; mf++) {
                float e0 = __expf(sfr[mf][0][0] * 0.125f);
                float e1 = __expf(sfr[mf][0][1] * 0.125f);
                float e2 = __expf(sfr[mf][0][2] * 0.125f);
                float e3 = __expf(sfr[mf][0][3] * 0.125f);
                float f0 = __expf(sfr[mf][1][0] * 0.125f);
                float f1 = __expf(sfr[mf][1][1] * 0.125f);
                float f2 = __expf(sfr[mf][1][2] * 0.125f);
                float f3 = __expf(sfr[mf][1][3] * 0.125f);
                __half2 he01 = __floats2half2_rn(e0, e1);
                __half2 he23 = __floats2half2_rn(e2, e3);
                __half2 hf01 = __floats2half2_rn(f0, f1);
                __half2 hf23 = __floats2half2_rn(f2, f3);
                ap[mf][0] = *reinterpret_cast<uint32_t*>(&he01);
                ap[mf][1] = *reinterpret_cast<uint32_t*>(&he23);
                ap[mf][2] = *reinterpret_cast<uint32_t*>(&hf01);
                ap[mf][3] = *reinterpret_cast<uint32_t*>(&hf23);
                lsum[mf][0] += __low2float(he01) + __high2float(he01)
                             + __low2float(hf01) + __high2float(hf01);
                lsum[mf][1] += __low2float(he23) + __high2float(he23)
                             + __low2float(hf23) + __high2float(hf23);
            }

#pragma unroll
            for (int nt2 = 0; nt2 < 4; nt2++) {
                const int kr = kt2 * 16 + (lane & 7) + ((lane >> 4) & 1) * 8;
                const uint32_t off = SWZ128(kr * 128 + nt2 * 32 + ((lane >> 3) & 1) * 16);
                uint32_t vh[4];
                LDSM_X4T(vh, kb + 8192 + off);
#pragma unroll
                for (int mf = 0; mf < 2; mf++) {
                    mma_f16(o[mf][2 * nt2],     ap[mf], vh[0], vh[2]);
                    mma_f16(o[mf][2 * nt2 + 1], ap[mf], vh[1], vh[3]);
                }
            }
        }
    };

    for (int i = 0; i < ntiles; i++) {
        CP_WAIT(0);
        __syncthreads();
        if (i == 0) {
#pragma unroll
            for (int mf = 0; mf < 2; mf++)
#pragma unroll
                for (int q = 0; q < 4; q++) {
                    const int row = wid * 32 + mf * 16 + (lane & 15);
                    const uint32_t off = SWZ128(row * 128 + q * 32 + (lane >> 4) * 16);
                    LDSM_X4(qh[mf][q], QSTG + off);
                }
        }
        if (i + 1 < ntiles) { load_kv(i + 1, (i + 1) & 1); CP_COMMIT(); }
        compute(BUF0 + (i & 1) * 16384);
    }

#pragma unroll
    for (int mf = 0; mf < 2; mf++) {
        lsum[mf][0] += __shfl_xor_sync(0xffffffffu, lsum[mf][0], 1);
        lsum[mf][0] += __shfl_xor_sync(0xffffffffu, lsum[mf][0], 2);
        lsum[mf][1] += __shfl_xor_sync(0xffffffffu, lsum[mf][1], 1);
        lsum[mf][1] += __shfl_xor_sync(0xffffffffu, lsum[mf][1], 2);
        const float inv0 = 1.f / lsum[mf][0], inv1 = 1.f / lsum[mf][1];

        const int r0 = wid * 32 + mf * 16 + (lane >> 2);
        const int t0g = qstart + r0;
        const size_t o0 = ((size_t)b * TT + t0g) * DD + h * DH + (lane & 3) * 2;
        const size_t o1 = o0 + (size_t)8 * DD;
#pragma unroll
        for (int nt = 0; nt < 8; nt++) {
            *(uint32_t*)(g_Oh + o0 + nt * 8) = pack_h2(o[mf][nt][0] * inv0, o[mf][nt][1] * inv0);
            *(uint32_t*)(g_Oh + o1 + nt * 8) = pack_h2(o[mf][nt][2] * inv1, o[mf][nt][3] * inv1);
        }
    }
}

// ---------------------------------------------------------------------------
// Four-chain pipeline with sliced input conversion:
//   s0: conv_w -> conv_xA(b0) -> qkvA(b0) -> attnLo(b0) -> projLo(b0)
//   s1: (e_w) conv_xB(b0) -> qkvB(b0) -> (eA0) attnHi(b0) -> projHi(b0)
//   s2: (e_w) conv_xA(b1) -> qkvA(b1) -> attnLo(b1) -> projLo(b1)
//   s3: (e_w) conv_xB(b1) -> qkvB(b1) -> (eA1) attnHi(b1) -> projHi(b1)
// Each chain converts only the x rows its qkv consumes; the serial head is
// just conv_w (~4MB). Streams/events created on first (non-captured) call.
// ---------------------------------------------------------------------------
extern "C" void kernel_launch(void* const* d_in, const int* in_sizes, int n_in,
                              void* d_out, int out_size)
{
    const float* x  = (const float*)d_in[0];
    const float* Wq = (const float*)d_in[1];
    const float* bq = (const float*)d_in[2];
    const float* Wk = (const float*)d_in[3];
    const float* bk = (const float*)d_in[4];
    const float* Wv = (const float*)d_in[5];
    const float* bv = (const float*)d_in[6];
    const float* Wo = (const float*)d_in[7];
    const float* bo = (const float*)d_in[8];
    float* out = (float*)d_out;

    __half *xh, *Wh, *Qh, *Kh, *Vh, *Oh;
    cudaGetSymbolAddress((void**)&xh, g_xh);
    cudaGetSymbolAddress((void**)&Wh, g_Wh);
    cudaGetSymbolAddress((void**)&Qh, g_Qh);
    cudaGetSymbolAddress((void**)&Kh, g_Kh);
    cudaGetSymbolAddress((void**)&Vh, g_Vh);
    cudaGetSymbolAddress((void**)&Oh, g_Oh);

    const int SMEM_QKV = 81920;            // 2 x 40K
    const int SMEM_P   = 49152;            // 2 x 24K
    const int SMEM_A   = 49152;            // 2 x 16K ring + 16K Q

    static cudaStream_t s1 = nullptr, s2 = nullptr, s3 = nullptr;
    static cudaEvent_t e_w = nullptr, eA0 = nullptr, eA1 = nullptr;
    static cudaEvent_t j1 = nullptr, j2 = nullptr, j3 = nullptr;
    static bool inited = false;
    if (!inited) {
        cudaFuncSetAttribute(qkv_gemm,  cudaFuncAttributeMaxDynamicSharedMemorySize, SMEM_QKV);
        cudaFuncSetAttribute(proj_gemm, cudaFuncAttributeMaxDynamicSharedMemorySize, SMEM_P);
        cudaFuncSetAttribute(attn_mma,  cudaFuncAttributeMaxDynamicSharedMemorySize, SMEM_A);
        cudaStreamCreateWithFlags(&s1, cudaStreamNonBlocking);
        cudaStreamCreateWithFlags(&s2, cudaStreamNonBlocking);
        cudaStreamCreateWithFlags(&s3, cudaStreamNonBlocking);
        cudaEventCreateWithFlags(&e_w, cudaEventDisableTiming);
        cudaEventCreateWithFlags(&eA0, cudaEventDisableTiming);
        cudaEventCreateWithFlags(&eA1, cudaEventDisableTiming);
        cudaEventCreateWithFlags(&j1, cudaEventDisableTiming);
        cudaEventCreateWithFlags(&j2, cudaEventDisableTiming);
        cudaEventCreateWithFlags(&j3, cudaEventDisableTiming);
        inited = true;
    }

    // Weights convert (small) gates all chains
    convert_w<<<(4 * NW4 + 255) / 256, 256>>>(
        (const float4*)Wq, (const float4*)Wk, (const float4*)Wv, (const float4*)Wo);
    cudaEventRecord(e_w, 0);
    cudaStreamWaitEvent(s1, e_w, 0);
    cudaStreamWaitEvent(s2, e_w, 0);
    cudaStreamWaitEvent(s3, e_w, 0);

    const __half* Wo_h = Wh + (size_t)3 * DD * DD;
    dim3 gA(DD / 64, 36, 1);   // t [0, 4608)
    dim3 gB(DD / 64, 28, 1);   // t [4608, 8192)
    dim3 gP(DD / 64, 32, 1);   // proj half: 4096 rows
    const int ATT_BLKS = HH * 32;

    // x-slice float4 extents: rowcount * DD / 4 = rowcount * 128
    const int N4_A = 4608 * 128;   // 589824
    const int N4_B = 3584 * 128;   // 458752

    // s0: conv_xA(b0) -> qkvA(b0) -> attnLo(b0) -> projLo(b0)
    convert_x<<<(N4_A + 255) / 256, 256, 0, 0>>>((const float4*)x, 0, N4_A);
    qkv_gemm<<<gA, 256, SMEM_QKV, 0>>>(xh, Wh, bq, bk, bv, Qh, Kh, Vh, 0);
    cudaEventRecord(eA0, 0);
    attn_mma<<<ATT_BLKS, 128, SMEM_A, 0>>>(0, 0);
    proj_gemm<<<gP, 256, SMEM_P, 0>>>(Oh, Wo_h, bo, out, 0);

    // s1: conv_xB(b0) -> qkvB(b0) -> (eA0) attnHi(b0) -> projHi(b0)
    convert_x<<<(N4_B + 255) / 256, 256, 0, s1>>>((const float4*)x, 4608 * 128, N4_B);
    qkv_gemm<<<gB, 256, SMEM_QKV, s1>>>(xh, Wh, bq, bk, bv, Qh, Kh, Vh, 4608);
    cudaStreamWaitEvent(s1, eA0, 0);
    attn_mma<<<ATT_BLKS, 128, SMEM_A, s1>>>(0, 32);
    proj_gemm<<<gP, 256, SMEM_P, s1>>>(Oh, Wo_h, bo, out, 4096);

    // s2: conv_xA(b1) -> qkvA(b1) -> attnLo(b1) -> projLo(b1)
    convert_x<<<(N4_A + 255) / 256, 256, 0, s2>>>((const float4*)x, TT * 128, N4_A);
    qkv_gemm<<<gA, 256, SMEM_QKV, s2>>>(xh, Wh, bq, bk, bv, Qh, Kh, Vh, TT);
    cudaEventRecord(eA1, s2);
    attn_mma<<<ATT_BLKS, 128, SMEM_A, s2>>>(1, 0);
    proj_gemm<<<gP, 256, SMEM_P, s2>>>(Oh, Wo_h, bo, out, TT);

    // s3: conv_xB(b1) -> qkvB(b1) -> (eA1) attnHi(b1) -> projHi(b1)
    convert_x<<<(N4_B + 255) / 256, 256, 0, s3>>>((const float4*)x, (TT + 4608) * 128, N4_B);
    qkv_gemm<<<gB, 256, SMEM_QKV, s3>>>(xh, Wh, bq, bk, bv, Qh, Kh, Vh, TT + 4608);
    cudaStreamWaitEvent(s3, eA1, 0);
    attn_mma<<<ATT_BLKS, 128, SMEM_A, s3>>>(1, 32);
    proj_gemm<<<gP, 256, SMEM_P, s3>>>(Oh, Wo_h, bo, out, TT + 4096);

    // Join all side streams back into s0
    cudaEventRecord(j1, s1);
    cudaEventRecord(j2, s2);
    cudaEventRecord(j3, s3);
    cudaStreamWaitEvent(0, j1, 0);
    cudaStreamWaitEvent(0, j2, 0);
    cudaStreamWaitEvent(0, j3, 0);
}

// round 16
// speedup vs baseline: 1.0485x; 1.0485x over previous
#include <cuda_runtime.h>
#include <cuda_fp16.h>
#include <cstdint>

// Problem constants
#define BB   2
#define TT   8192
#define DD   512
#define HH   8
#define WW   256
#define DH   64
#define NC   32

// ---------------------------------------------------------------------------
// Static device scratch (single rn-fp16 representations; err ~2^-12)
// ---------------------------------------------------------------------------
__device__ __half g_xh[(size_t)BB * TT * DD];
__device__ __half g_Wh[4 * DD * DD];                // q,k,v,o stacked
__device__ __half g_Qh[(size_t)BB * HH * TT * DH];
__device__ __half g_Kh[(size_t)BB * HH * TT * DH];
__device__ __half g_Vh[(size_t)BB * HH * TT * DH];
__device__ __half g_Oh[(size_t)BB * TT * DD];

// ---------------------------------------------------------------------------
// Helpers (base sm_103 features only: mma.sync / ldmatrix / cp.async)
// ---------------------------------------------------------------------------
__device__ __forceinline__ uint32_t smem_to_u32(const void* p) {
    uint32_t a;
    asm("{ .reg .u64 t; cvta.to.shared.u64 t, %1; cvt.u32.u64 %0, t; }"
        : "=r"(a) : "l"(p));
    return a;
}

#define SWZ128(b) ((b) ^ (((b) >> 3) & 0x70))

__device__ __forceinline__ void cp16(uint32_t dst, const void* src) {
    asm volatile("cp.async.cg.shared.global [%0], [%1], 16;" :: "r"(dst), "l"(src) : "memory");
}
#define CP_COMMIT() asm volatile("cp.async.commit_group;" ::: "memory")
#define CP_WAIT(N)  asm volatile("cp.async.wait_group %0;" :: "n"(N) : "memory")

#define LDSM_X4(R, ADDR) \
    asm volatile("ldmatrix.sync.aligned.m8n8.x4.shared.b16 {%0,%1,%2,%3}, [%4];" \
        : "=r"((R)[0]), "=r"((R)[1]), "=r"((R)[2]), "=r"((R)[3]) : "r"(ADDR))

#define LDSM_X4T(R, ADDR) \
    asm volatile("ldmatrix.sync.aligned.m8n8.x4.trans.shared.b16 {%0,%1,%2,%3}, [%4];" \
        : "=r"((R)[0]), "=r"((R)[1]), "=r"((R)[2]), "=r"((R)[3]) : "r"(ADDR))

__device__ __forceinline__ void mma_f16(float c[4], const uint32_t a[4],
                                        uint32_t b0, uint32_t b1) {
    asm volatile(
        "mma.sync.aligned.m16n8k16.row.col.f32.f16.f16.f32 "
        "{%0,%1,%2,%3}, {%4,%5,%6,%7}, {%8,%9}, {%0,%1,%2,%3};"
        : "+f"(c[0]), "+f"(c[1]), "+f"(c[2]), "+f"(c[3])
        : "r"(a[0]), "r"(a[1]), "r"(a[2]), "r"(a[3]), "r"(b0), "r"(b1));
}

__device__ __forceinline__ uint32_t pack_h2(float a, float b) {
    __half2 h = __floats2half2_rn(a, b);
    return *reinterpret_cast<uint32_t*>(&h);
}

// ---------------------------------------------------------------------------
// Input prep: x and 4 W matrices -> rn fp16 (monolithic; R14 schedule)
// ---------------------------------------------------------------------------
#define NX4 ((BB * TT * DD) / 4)
#define NW4 ((DD * DD) / 4)

__global__ void __launch_bounds__(256) convert_inputs(
    const float4* __restrict__ x,
    const float4* __restrict__ wq, const float4* __restrict__ wk,
    const float4* __restrict__ wv, const float4* __restrict__ wo)
{
    int i = blockIdx.x * 256 + threadIdx.x;
    float4 a;
    uint32_t* dst;
    if (i < NX4) {
        a = x[i];
        dst = (uint32_t*)g_xh + 2 * i;
    } else {
        int j = i - NX4;
        if (j >= 4 * NW4) return;
        int w = j >> 16;            // NW4 = 65536
        int r = j & (NW4 - 1);
        const float4* ws[4] = { wq, wk, wv, wo };
        a = ws[w][r];
        dst = (uint32_t*)g_Wh + 2 * (w * NW4 + r);
    }
    dst[0] = pack_h2(a.x, a.y);
    dst[1] = pack_h2(a.z, a.w);
}

// ---------------------------------------------------------------------------
// Fused QKV GEMM (R12 shape), m-sliced via m_off (absolute 128-row tiles).
// A fragments register-resident across z; ratio 3.0 MMA/LDSM.
// Stage = A 16K + 3 x B 8K = 40K, double buffered 80K -> 2 CTAs/SM.
// ---------------------------------------------------------------------------
__global__ void __launch_bounds__(256, 2) qkv_gemm(
    const __half* __restrict__ A, const __half* __restrict__ WB,
    const float* __restrict__ bq, const float* __restrict__ bk,
    const float* __restrict__ bv,
    __half* __restrict__ outQ, __half* __restrict__ outK,
    __half* __restrict__ outV, int m_off)
{
    constexpr int STG = 40960;
    extern __shared__ char smc[];
    const uint32_t su = smem_to_u32(smc);
    const int tid = threadIdx.x, lane = tid & 31, wid = tid >> 5;
    const int wm = wid & 3, wn = wid >> 2;
    const int bm = m_off + blockIdx.y * 128, bn = blockIdx.x * 64;

    const __half* srcA = A + (size_t)bm * DD;
    const __half* srcB[3] = {
        WB + 0 * (size_t)DD * DD + (size_t)bn * DD,
        WB + 1 * (size_t)DD * DD + (size_t)bn * DD,
        WB + 2 * (size_t)DD * DD + (size_t)bn * DD };

    auto load_stage = [&](int s, int buf) {
        const uint32_t base = su + buf * STG;
        const int k0 = s * 64;
#pragma unroll
        for (int p = 0; p < 10; p++) {
            int idx = p * 256 + tid;
            if (idx >= 2560) break;
            if (idx < 1024) {
                int row = idx >> 3, col = idx & 7;
                cp16(base + SWZ128(row * 128 + col * 16),
                     srcA + (size_t)row * DD + k0 + col * 8);
            } else {
                int j = idx - 1024;
                int z = j >> 9, row = (j >> 3) & 63, col = j & 7;
                cp16(base + 16384 + z * 8192 + SWZ128(row * 128 + col * 16),
                     srcB[z] + (size_t)row * DD + k0 + col * 8);
            }
        }
    };

    float c[3][2][4][4] = {};

    load_stage(0, 0); CP_COMMIT();

    for (int s = 0; s < 8; s++) {
        CP_WAIT(0);
        __syncthreads();
        if (s < 7) { load_stage(s + 1, (s + 1) & 1); CP_COMMIT(); }
        const uint32_t bA = su + (s & 1) * STG;
#pragma unroll
        for (int q = 0; q < 4; q++) {
            uint32_t ah[2][4];
#pragma unroll
            for (int mt = 0; mt < 2; mt++) {
                const int row = wm * 32 + mt * 16 + (lane & 15);
                const uint32_t off = SWZ128(row * 128 + q * 32 + (lane >> 4) * 16);
                LDSM_X4(ah[mt], bA + off);
            }
#pragma unroll
            for (int z = 0; z < 3; z++) {
                const uint32_t bB = bA + 16384 + z * 8192;
#pragma unroll
                for (int nt2 = 0; nt2 < 2; nt2++) {
                    const int n = wn * 32 + nt2 * 16 + (lane & 7) + ((lane >> 4) & 1) * 8;
                    const uint32_t off = SWZ128(n * 128 + q * 32 + ((lane >> 3) & 1) * 16);
                    uint32_t bh[4];
                    LDSM_X4(bh, bB + off);
#pragma unroll
                    for (int mt = 0; mt < 2; mt++) {
                        mma_f16(c[z][mt][2 * nt2],     ah[mt], bh[0], bh[1]);
                        mma_f16(c[z][mt][2 * nt2 + 1], ah[mt], bh[2], bh[3]);
                    }
                }
            }
        }
    }

#pragma unroll
    for (int z = 0; z < 3; z++) {
        const float* bias = (z == 0) ? bq : (z == 1 ? bk : bv);
        __half* dstH = (z == 0) ? outQ : (z == 1 ? outK : outV);
#pragma unroll
        for (int mt = 0; mt < 2; mt++) {
            const int r0 = bm + wm * 32 + mt * 16 + (lane >> 2);
#pragma unroll
            for (int nt = 0; nt < 4; nt++) {
                const int n = bn + wn * 32 + nt * 8 + (lane & 3) * 2;
                const float b0v = bias[n], b1v = bias[n + 1];
                const float v0 = c[z][mt][nt][0] + b0v, v1 = c[z][mt][nt][1] + b1v;
                const float v2 = c[z][mt][nt][2] + b0v, v3 = c[z][mt][nt][3] + b1v;
                const int hh = n >> 6, j = n & 63;
                const int bq_ = r0 >> 13, t = r0 & (TT - 1);
                const size_t off0 = (((size_t)bq_ * HH + hh) * TT + t) * DH + j;
                const size_t off1 = off0 + 8 * DH;
                *(uint32_t*)(dstH + off0) = pack_h2(v0, v1);
                *(uint32_t*)(dstH + off1) = pack_h2(v2, v3);
            }
        }
    }
}

// ---------------------------------------------------------------------------
// Output projection GEMM, m-sliced via m_off.
// ---------------------------------------------------------------------------
__global__ void __launch_bounds__(256, 2) proj_gemm(
    const __half* __restrict__ A, const __half* __restrict__ WB,
    const float* __restrict__ bias, float* __restrict__ outF, int m_off)
{
    constexpr int STG = 24576;
    extern __shared__ char smc[];
    const uint32_t su = smem_to_u32(smc);
    const int tid = threadIdx.x, lane = tid & 31, wid = tid >> 5;
    const int wm = wid & 3, wn = wid >> 2;
    const int bm = m_off + blockIdx.y * 128, bn = blockIdx.x * 64;

    const __half* srcA = A + (size_t)bm * DD;
    const __half* srcB = WB + (size_t)bn * DD;

    auto load_stage = [&](int s, int buf) {
        const uint32_t base = su + buf * STG;
        const int k0 = s * 64;
#pragma unroll
        for (int p = 0; p < 6; p++) {
            int idx = p * 256 + tid;
            if (idx < 1024) {
                int row = idx >> 3, col = idx & 7;
                cp16(base + SWZ128(row * 128 + col * 16),
                     srcA + (size_t)row * DD + k0 + col * 8);
            } else {
                int j = idx - 1024;
                int row = j >> 3, col = j & 7;
                cp16(base + 16384 + SWZ128(row * 128 + col * 16),
                     srcB + (size_t)row * DD + k0 + col * 8);
            }
        }
    };

    float c[2][4][4] = {};

    load_stage(0, 0); CP_COMMIT();

    for (int s = 0; s < 8; s++) {
        CP_WAIT(0);
        __syncthreads();
        if (s < 7) { load_stage(s + 1, (s + 1) & 1); CP_COMMIT(); }
        const uint32_t bA = su + (s & 1) * STG;
        const uint32_t bB = bA + 16384;
#pragma unroll
        for (int q = 0; q < 4; q++) {
            uint32_t ah[2][4];
#pragma unroll
            for (int mt = 0; mt < 2; mt++) {
                const int row = wm * 32 + mt * 16 + (lane & 15);
                const uint32_t off = SWZ128(row * 128 + q * 32 + (lane >> 4) * 16);
                LDSM_X4(ah[mt], bA + off);
            }
#pragma unroll
            for (int nt2 = 0; nt2 < 2; nt2++) {
                const int n = wn * 32 + nt2 * 16 + (lane & 7) + ((lane >> 4) & 1) * 8;
                const uint32_t off = SWZ128(n * 128 + q * 32 + ((lane >> 3) & 1) * 16);
                uint32_t bh[4];
                LDSM_X4(bh, bB + off);
#pragma unroll
                for (int mt = 0; mt < 2; mt++) {
                    mma_f16(c[mt][2 * nt2],     ah[mt], bh[0], bh[1]);
                    mma_f16(c[mt][2 * nt2 + 1], ah[mt], bh[2], bh[3]);
                }
            }
        }
    }

#pragma unroll
    for (int mt = 0; mt < 2; mt++) {
        const int r0 = bm + wm * 32 + mt * 16 + (lane >> 2);
#pragma unroll
        for (int nt = 0; nt < 4; nt++) {
            const int n = bn + wn * 32 + nt * 8 + (lane & 3) * 2;
            const float b0v = bias[n], b1v = bias[n + 1];
            float2 p0; p0.x = c[mt][nt][0] + b0v; p0.y = c[mt][nt][1] + b1v;
            float2 p1; p1.x = c[mt][nt][2] + b0v; p1.y = c[mt][nt][3] + b1v;
            *(float2*)(outF + (size_t)r0 * DD + n) = p0;
            *(float2*)(outF + (size_t)(r0 + 8) * DD + n) = p1;
        }
    }
}

// ---------------------------------------------------------------------------
// Local attention (R11/R14 shape), sliced via bsel + qb_off.
// NEW: lsum computed on the TENSOR pipe via MMA with an all-ones B fragment
// (row sums of the rounded P; fp32 accumulation of the same fp16 values as
// the old scalar path, just re-associated). Removes 64 cvt + 64 fadd per
// tile per warp AND the final shuffle reduction (all output columns of the
// ones-MMA are identical, so each thread holds its row's full sum).
// ---------------------------------------------------------------------------
__global__ void __launch_bounds__(128, 3) attn_mma(int bsel, int qb_off)
{
    extern __shared__ char smc[];
    const uint32_t su = smem_to_u32(smc);
    const int tid = threadIdx.x, lane = tid & 31, wid = tid >> 5;
    const int bid = blockIdx.x;                // [0, 256)
    const int qb = (bid & 31) + qb_off;
    const int h = bid >> 5;
    const int b = bsel;
    const int qstart = qb * 128;
    const int c = qb >> 1;

    const size_t hb = ((size_t)(b * HH + h)) * TT * DH;
    const __half* Qp = g_Qh + hb;
    const __half* Kp = g_Kh + hb;
    const __half* Vp = g_Vh + hb;

    const int k0 = (c == 0) ? 0 : (c - 1) * WW;
    const int k1 = (c == NC - 1) ? TT : (c + 2) * WW;
    const int ntiles = (k1 - k0) >> 6;

    const uint32_t BUF0 = su;
    const uint32_t QSTG = su + 2 * 16384;

    const uint32_t ONES = 0x3C003C00u;     // half2(1.0, 1.0)

    auto load_kv = [&](int i, int buf) {
        const int kt = k0 + i * 64;
        const uint32_t base = BUF0 + buf * 16384;
#pragma unroll
        for (int p = 0; p < 8; p++) {
            int idx = p * 128 + tid;
            int mtx = idx >> 9, row = (idx >> 3) & 63, col = idx & 7;
            cp16(base + mtx * 8192 + SWZ128(row * 128 + col * 16),
                 (mtx ? Vp : Kp) + (size_t)(kt + row) * DH + col * 8);
        }
    };

#pragma unroll
    for (int p = 0; p < 8; p++) {
        int idx = p * 128 + tid;
        int row = idx >> 3, col = idx & 7;
        cp16(QSTG + SWZ128(row * 128 + col * 16),
             Qp + (size_t)(qstart + row) * DH + col * 8);
    }
    load_kv(0, 0);
    CP_COMMIT();

    float o[2][8][4] = {};
    float ls[2][4] = {};         // ones-MMA accumulators: [0]=row r, [2]=row r+8
    uint32_t qh[2][4][4];

    auto compute = [&](uint32_t kb) {
#pragma unroll
        for (int kt2 = 0; kt2 < 4; kt2++) {
            float sfr[2][2][4] = {};
#pragma unroll
            for (int q = 0; q < 4; q++) {
                const int n = kt2 * 16 + (lane & 7) + ((lane >> 4) & 1) * 8;
                const uint32_t off = SWZ128(n * 128 + q * 32 + ((lane >> 3) & 1) * 16);
                uint32_t kh[4];
                LDSM_X4(kh, kb + off);
#pragma unroll
                for (int mf = 0; mf < 2; mf++) {
                    mma_f16(sfr[mf][0], qh[mf][q], kh[0], kh[1]);
                    mma_f16(sfr[mf][1], qh[mf][q], kh[2], kh[3]);
                }
            }

            // p = rn_fp16(exp(s/8)); row sums via ones-MMA on the tensor pipe
            uint32_t ap[2][4];
#pragma unroll
            for (int mf = 0; mf < 2; mf++) {
                float e0 = __expf(sfr[mf][0][0] * 0.125f);
                float e1 = __expf(sfr[mf][0][1] * 0.125f);
                float e2 = __expf(sfr[mf][0][2] * 0.125f);
                float e3 = __expf(sfr[mf][0][3] * 0.125f);
                float f0 = __expf(sfr[mf][1][0] * 0.125f);
                float f1 = __expf(sfr[mf][1][1] * 0.125f);
                float f2 = __expf(sfr[mf][1][2] * 0.125f);
                float f3 = __expf(sfr[mf][1][3] * 0.125f);
                ap[mf][0] = pack_h2(e0, e1);
                ap[mf][1] = pack_h2(e2, e3);
                ap[mf][2] = pack_h2(f0, f1);
                ap[mf][3] = pack_h2(f2, f3);
                mma_f16(ls[mf], ap[mf], ONES, ONES);
            }

#pragma unroll
            for (int nt2 = 0; nt2 < 4; nt2++) {
                const int kr = kt2 * 16 + (lane & 7) + ((lane >> 4) & 1) * 8;
                const uint32_t off = SWZ128(kr * 128 + nt2 * 32 + ((lane >> 3) & 1) * 16);
                uint32_t vh[4];
                LDSM_X4T(vh, kb + 8192 + off);
#pragma unroll
                for (int mf = 0; mf < 2; mf++) {
                    mma_f16(o[mf][2 * nt2],     ap[mf], vh[0], vh[2]);
                    mma_f16(o[mf][2 * nt2 + 1], ap[mf], vh[1], vh[3]);
                }
            }
        }
    };

    for (int i = 0; i < ntiles; i++) {
        CP_WAIT(0);
        __syncthreads();
        if (i == 0) {
#pragma unroll
            for (int mf = 0; mf < 2; mf++)
#pragma unroll
                for (int q = 0; q < 4; q++) {
                    const int row = wid * 32 + mf * 16 + (lane & 15);
                    const uint32_t off = SWZ128(row * 128 + q * 32 + (lane >> 4) * 16);
                    LDSM_X4(qh[mf][q], QSTG + off);
                }
        }
        if (i + 1 < ntiles) { load_kv(i + 1, (i + 1) & 1); CP_COMMIT(); }
        compute(BUF0 + (i & 1) * 16384);
    }

    // normalize + store (rn fp16 to [B,T,D]); no shuffle reduce needed:
    // ls[mf][0] = full key-sum for row r, ls[mf][2] = for row r+8.
#pragma unroll
    for (int mf = 0; mf < 2; mf++) {
        const float inv0 = 1.f / ls[mf][0], inv1 = 1.f / ls[mf][2];

        const int r0 = wid * 32 + mf * 16 + (lane >> 2);
        const int t0g = qstart + r0;
        const size_t o0 = ((size_t)b * TT + t0g) * DD + h * DH + (lane & 3) * 2;
        const size_t o1 = o0 + (size_t)8 * DD;
#pragma unroll
        for (int nt = 0; nt < 8; nt++) {
            *(uint32_t*)(g_Oh + o0 + nt * 8) = pack_h2(o[mf][nt][0] * inv0, o[mf][nt][1] * inv0);
            *(uint32_t*)(g_Oh + o1 + nt * 8) = pack_h2(o[mf][nt][2] * inv1, o[mf][nt][3] * inv1);
        }
    }
}

// ---------------------------------------------------------------------------
// Four-chain pipeline (R14 schedule, the best known):
//   qkvA(b) = t [0,4608)   -> attnLo(b) (window <= 4352)  -> projLo(b)
//   qkvB(b) = t [4608,8192) + qkvA(b) -> attnHi(b) (window >= 3840) -> projHi(b)
// ---------------------------------------------------------------------------
extern "C" void kernel_launch(void* const* d_in, const int* in_sizes, int n_in,
                              void* d_out, int out_size)
{
    const float* x  = (const float*)d_in[0];
    const float* Wq = (const float*)d_in[1];
    const float* bq = (const float*)d_in[2];
    const float* Wk = (const float*)d_in[3];
    const float* bk = (const float*)d_in[4];
    const float* Wv = (const float*)d_in[5];
    const float* bv = (const float*)d_in[6];
    const float* Wo = (const float*)d_in[7];
    const float* bo = (const float*)d_in[8];
    float* out = (float*)d_out;

    __half *xh, *Wh, *Qh, *Kh, *Vh, *Oh;
    cudaGetSymbolAddress((void**)&xh, g_xh);
    cudaGetSymbolAddress((void**)&Wh, g_Wh);
    cudaGetSymbolAddress((void**)&Qh, g_Qh);
    cudaGetSymbolAddress((void**)&Kh, g_Kh);
    cudaGetSymbolAddress((void**)&Vh, g_Vh);
    cudaGetSymbolAddress((void**)&Oh, g_Oh);

    const int SMEM_QKV = 81920;            // 2 x 40K
    const int SMEM_P   = 49152;            // 2 x 24K
    const int SMEM_A   = 49152;            // 2 x 16K ring + 16K Q

    static cudaStream_t s1 = nullptr, s2 = nullptr, s3 = nullptr;
    static cudaEvent_t e_conv = nullptr, eA0 = nullptr, eA1 = nullptr;
    static cudaEvent_t j1 = nullptr, j2 = nullptr, j3 = nullptr;
    static bool inited = false;
    if (!inited) {
        cudaFuncSetAttribute(qkv_gemm,  cudaFuncAttributeMaxDynamicSharedMemorySize, SMEM_QKV);
        cudaFuncSetAttribute(proj_gemm, cudaFuncAttributeMaxDynamicSharedMemorySize, SMEM_P);
        cudaFuncSetAttribute(attn_mma,  cudaFuncAttributeMaxDynamicSharedMemorySize, SMEM_A);
        cudaStreamCreateWithFlags(&s1, cudaStreamNonBlocking);
        cudaStreamCreateWithFlags(&s2, cudaStreamNonBlocking);
        cudaStreamCreateWithFlags(&s3, cudaStreamNonBlocking);
        cudaEventCreateWithFlags(&e_conv, cudaEventDisableTiming);
        cudaEventCreateWithFlags(&eA0, cudaEventDisableTiming);
        cudaEventCreateWithFlags(&eA1, cudaEventDisableTiming);
        cudaEventCreateWithFlags(&j1, cudaEventDisableTiming);
        cudaEventCreateWithFlags(&j2, cudaEventDisableTiming);
        cudaEventCreateWithFlags(&j3, cudaEventDisableTiming);
        inited = true;
    }

    // Convert on s0, fork to s1..s3
    const int ntot = NX4 + 4 * NW4;
    convert_inputs<<<(ntot + 255) / 256, 256>>>(
        (const float4*)x, (const float4*)Wq, (const float4*)Wk,
        (const float4*)Wv, (const float4*)Wo);
    cudaEventRecord(e_conv, 0);
    cudaStreamWaitEvent(s1, e_conv, 0);
    cudaStreamWaitEvent(s2, e_conv, 0);
    cudaStreamWaitEvent(s3, e_conv, 0);

    const __half* Wo_h = Wh + (size_t)3 * DD * DD;
    dim3 gA(DD / 64, 36, 1);   // t [0, 4608)
    dim3 gB(DD / 64, 28, 1);   // t [4608, 8192)
    dim3 gP(DD / 64, 32, 1);   // proj half: 4096 rows
    const int ATT_BLKS = HH * 32;

    // s0: qkvA(b0) -> attnLo(b0) -> projLo(b0)
    qkv_gemm<<<gA, 256, SMEM_QKV, 0>>>(xh, Wh, bq, bk, bv, Qh, Kh, Vh, 0);
    cudaEventRecord(eA0, 0);
    attn_mma<<<ATT_BLKS, 128, SMEM_A, 0>>>(0, 0);
    proj_gemm<<<gP, 256, SMEM_P, 0>>>(Oh, Wo_h, bo, out, 0);

    // s1: qkvB(b0); wait qkvA(b0) -> attnHi(b0) -> projHi(b0)
    qkv_gemm<<<gB, 256, SMEM_QKV, s1>>>(xh, Wh, bq, bk, bv, Qh, Kh, Vh, 4608);
    cudaStreamWaitEvent(s1, eA0, 0);
    attn_mma<<<ATT_BLKS, 128, SMEM_A, s1>>>(0, 32);
    proj_gemm<<<gP, 256, SMEM_P, s1>>>(Oh, Wo_h, bo, out, 4096);

    // s2: qkvA(b1) -> attnLo(b1) -> projLo(b1)
    qkv_gemm<<<gA, 256, SMEM_QKV, s2>>>(xh, Wh, bq, bk, bv, Qh, Kh, Vh, TT);
    cudaEventRecord(eA1, s2);
    attn_mma<<<ATT_BLKS, 128, SMEM_A, s2>>>(1, 0);
    proj_gemm<<<gP, 256, SMEM_P, s2>>>(Oh, Wo_h, bo, out, TT);

    // s3: qkvB(b1); wait qkvA(b1) -> attnHi(b1) -> projHi(b1)
    qkv_gemm<<<gB, 256, SMEM_QKV, s3>>>(xh, Wh, bq, bk, bv, Qh, Kh, Vh, TT + 4608);
    cudaStreamWaitEvent(s3, eA1, 0);
    attn_mma<<<ATT_BLKS, 128, SMEM_A, s3>>>(1, 32);
    proj_gemm<<<gP, 256, SMEM_P, s3>>>(Oh, Wo_h, bo, out, TT + 4096);

    // Join all side streams back into s0
    cudaEventRecord(j1, s1);
    cudaEventRecord(j2, s2);
    cudaEventRecord(j3, s3);
    cudaStreamWaitEvent(0, j1, 0);
    cudaStreamWaitEvent(0, j2, 0);
    cudaStreamWaitEvent(0, j3, 0);
}

// round 17
// speedup vs baseline: 1.0859x; 1.0357x over previous
#include <cuda_runtime.h>
#include <cuda_fp16.h>
#include <cstdint>

// Problem constants
#define BB   2
#define TT   8192
#define DD   512
#define HH   8
#define WW   256
#define DH   64
#define NC   32

// ---------------------------------------------------------------------------
// Static device scratch (single rn-fp16 representations; err ~2^-12)
// g_Qh holds Q PRE-SCALED by 0.125*log2(e) so attention uses raw ex2.
// ---------------------------------------------------------------------------
__device__ __half g_xh[(size_t)BB * TT * DD];
__device__ __half g_Wh[4 * DD * DD];                // q,k,v,o stacked
__device__ __half g_Qh[(size_t)BB * HH * TT * DH];
__device__ __half g_Kh[(size_t)BB * HH * TT * DH];
__device__ __half g_Vh[(size_t)BB * HH * TT * DH];
__device__ __half g_Oh[(size_t)BB * TT * DD];

// ---------------------------------------------------------------------------
// Helpers (base sm_103 features only: mma.sync / ldmatrix / cp.async)
// ---------------------------------------------------------------------------
__device__ __forceinline__ uint32_t smem_to_u32(const void* p) {
    uint32_t a;
    asm("{ .reg .u64 t; cvta.to.shared.u64 t, %1; cvt.u32.u64 %0, t; }"
        : "=r"(a) : "l"(p));
    return a;
}

#define SWZ128(b) ((b) ^ (((b) >> 3) & 0x70))

__device__ __forceinline__ void cp16(uint32_t dst, const void* src) {
    asm volatile("cp.async.cg.shared.global [%0], [%1], 16;" :: "r"(dst), "l"(src) : "memory");
}
#define CP_COMMIT() asm volatile("cp.async.commit_group;" ::: "memory")
#define CP_WAIT(N)  asm volatile("cp.async.wait_group %0;" :: "n"(N) : "memory")

#define LDSM_X4(R, ADDR) \
    asm volatile("ldmatrix.sync.aligned.m8n8.x4.shared.b16 {%0,%1,%2,%3}, [%4];" \
        : "=r"((R)[0]), "=r"((R)[1]), "=r"((R)[2]), "=r"((R)[3]) : "r"(ADDR))

#define LDSM_X4T(R, ADDR) \
    asm volatile("ldmatrix.sync.aligned.m8n8.x4.trans.shared.b16 {%0,%1,%2,%3}, [%4];" \
        : "=r"((R)[0]), "=r"((R)[1]), "=r"((R)[2]), "=r"((R)[3]) : "r"(ADDR))

__device__ __forceinline__ void mma_f16(float c[4], const uint32_t a[4],
                                        uint32_t b0, uint32_t b1) {
    asm volatile(
        "mma.sync.aligned.m16n8k16.row.col.f32.f16.f16.f32 "
        "{%0,%1,%2,%3}, {%4,%5,%6,%7}, {%8,%9}, {%0,%1,%2,%3};"
        : "+f"(c[0]), "+f"(c[1]), "+f"(c[2]), "+f"(c[3])
        : "r"(a[0]), "r"(a[1]), "r"(a[2]), "r"(a[3]), "r"(b0), "r"(b1));
}

__device__ __forceinline__ uint32_t pack_h2(float a, float b) {
    __half2 h = __floats2half2_rn(a, b);
    return *reinterpret_cast<uint32_t*>(&h);
}

__device__ __forceinline__ float ex2f(float x) {
    float y;
    asm("ex2.approx.f32 %0, %1;" : "=f"(y) : "f"(x));
    return y;
}

// 0.125 * log2(e): folded into Q at the QKV epilogue
#define QSCALE 0.1803368801111244f

// ---------------------------------------------------------------------------
// Input prep: x and 4 W matrices -> rn fp16 (monolithic; R14 schedule)
// ---------------------------------------------------------------------------
#define NX4 ((BB * TT * DD) / 4)
#define NW4 ((DD * DD) / 4)

__global__ void __launch_bounds__(256) convert_inputs(
    const float4* __restrict__ x,
    const float4* __restrict__ wq, const float4* __restrict__ wk,
    const float4* __restrict__ wv, const float4* __restrict__ wo)
{
    int i = blockIdx.x * 256 + threadIdx.x;
    float4 a;
    uint32_t* dst;
    if (i < NX4) {
        a = x[i];
        dst = (uint32_t*)g_xh + 2 * i;
    } else {
        int j = i - NX4;
        if (j >= 4 * NW4) return;
        int w = j >> 16;            // NW4 = 65536
        int r = j & (NW4 - 1);
        const float4* ws[4] = { wq, wk, wv, wo };
        a = ws[w][r];
        dst = (uint32_t*)g_Wh + 2 * (w * NW4 + r);
    }
    dst[0] = pack_h2(a.x, a.y);
    dst[1] = pack_h2(a.z, a.w);
}

// ---------------------------------------------------------------------------
// Fused QKV GEMM (R12 shape), m-sliced via m_off (absolute 128-row tiles).
// A fragments register-resident across z; ratio 3.0 MMA/LDSM.
// Stage = A 16K + 3 x B 8K = 40K, double buffered 80K -> 2 CTAs/SM.
// Q output (z==0) is pre-scaled by QSCALE so attn uses raw ex2.
// ---------------------------------------------------------------------------
__global__ void __launch_bounds__(256, 2) qkv_gemm(
    const __half* __restrict__ A, const __half* __restrict__ WB,
    const float* __restrict__ bq, const float* __restrict__ bk,
    const float* __restrict__ bv,
    __half* __restrict__ outQ, __half* __restrict__ outK,
    __half* __restrict__ outV, int m_off)
{
    constexpr int STG = 40960;
    extern __shared__ char smc[];
    const uint32_t su = smem_to_u32(smc);
    const int tid = threadIdx.x, lane = tid & 31, wid = tid >> 5;
    const int wm = wid & 3, wn = wid >> 2;
    const int bm = m_off + blockIdx.y * 128, bn = blockIdx.x * 64;

    const __half* srcA = A + (size_t)bm * DD;
    const __half* srcB[3] = {
        WB + 0 * (size_t)DD * DD + (size_t)bn * DD,
        WB + 1 * (size_t)DD * DD + (size_t)bn * DD,
        WB + 2 * (size_t)DD * DD + (size_t)bn * DD };

    auto load_stage = [&](int s, int buf) {
        const uint32_t base = su + buf * STG;
        const int k0 = s * 64;
#pragma unroll
        for (int p = 0; p < 10; p++) {
            int idx = p * 256 + tid;
            if (idx >= 2560) break;
            if (idx < 1024) {
                int row = idx >> 3, col = idx & 7;
                cp16(base + SWZ128(row * 128 + col * 16),
                     srcA + (size_t)row * DD + k0 + col * 8);
            } else {
                int j = idx - 1024;
                int z = j >> 9, row = (j >> 3) & 63, col = j & 7;
                cp16(base + 16384 + z * 8192 + SWZ128(row * 128 + col * 16),
                     srcB[z] + (size_t)row * DD + k0 + col * 8);
            }
        }
    };

    float c[3][2][4][4] = {};

    load_stage(0, 0); CP_COMMIT();

    for (int s = 0; s < 8; s++) {
        CP_WAIT(0);
        __syncthreads();
        if (s < 7) { load_stage(s + 1, (s + 1) & 1); CP_COMMIT(); }
        const uint32_t bA = su + (s & 1) * STG;
#pragma unroll
        for (int q = 0; q < 4; q++) {
            uint32_t ah[2][4];
#pragma unroll
            for (int mt = 0; mt < 2; mt++) {
                const int row = wm * 32 + mt * 16 + (lane & 15);
                const uint32_t off = SWZ128(row * 128 + q * 32 + (lane >> 4) * 16);
                LDSM_X4(ah[mt], bA + off);
            }
#pragma unroll
            for (int z = 0; z < 3; z++) {
                const uint32_t bB = bA + 16384 + z * 8192;
#pragma unroll
                for (int nt2 = 0; nt2 < 2; nt2++) {
                    const int n = wn * 32 + nt2 * 16 + (lane & 7) + ((lane >> 4) & 1) * 8;
                    const uint32_t off = SWZ128(n * 128 + q * 32 + ((lane >> 3) & 1) * 16);
                    uint32_t bh[4];
                    LDSM_X4(bh, bB + off);
#pragma unroll
                    for (int mt = 0; mt < 2; mt++) {
                        mma_f16(c[z][mt][2 * nt2],     ah[mt], bh[0], bh[1]);
                        mma_f16(c[z][mt][2 * nt2 + 1], ah[mt], bh[2], bh[3]);
                    }
                }
            }
        }
    }

#pragma unroll
    for (int z = 0; z < 3; z++) {
        const float* bias = (z == 0) ? bq : (z == 1 ? bk : bv);
        __half* dstH = (z == 0) ? outQ : (z == 1 ? outK : outV);
        const float scl = (z == 0) ? QSCALE : 1.0f;
#pragma unroll
        for (int mt = 0; mt < 2; mt++) {
            const int r0 = bm + wm * 32 + mt * 16 + (lane >> 2);
#pragma unroll
            for (int nt = 0; nt < 4; nt++) {
                const int n = bn + wn * 32 + nt * 8 + (lane & 3) * 2;
                const float b0v = bias[n], b1v = bias[n + 1];
                const float v0 = (c[z][mt][nt][0] + b0v) * scl, v1 = (c[z][mt][nt][1] + b1v) * scl;
                const float v2 = (c[z][mt][nt][2] + b0v) * scl, v3 = (c[z][mt][nt][3] + b1v) * scl;
                const int hh = n >> 6, j = n & 63;
                const int bq_ = r0 >> 13, t = r0 & (TT - 1);
                const size_t off0 = (((size_t)bq_ * HH + hh) * TT + t) * DH + j;
                const size_t off1 = off0 + 8 * DH;
                *(uint32_t*)(dstH + off0) = pack_h2(v0, v1);
                *(uint32_t*)(dstH + off1) = pack_h2(v2, v3);
            }
        }
    }
}

// ---------------------------------------------------------------------------
// Output projection GEMM, m-sliced via m_off.
// ---------------------------------------------------------------------------
__global__ void __launch_bounds__(256, 2) proj_gemm(
    const __half* __restrict__ A, const __half* __restrict__ WB,
    const float* __restrict__ bias, float* __restrict__ outF, int m_off)
{
    constexpr int STG = 24576;
    extern __shared__ char smc[];
    const uint32_t su = smem_to_u32(smc);
    const int tid = threadIdx.x, lane = tid & 31, wid = tid >> 5;
    const int wm = wid & 3, wn = wid >> 2;
    const int bm = m_off + blockIdx.y * 128, bn = blockIdx.x * 64;

    const __half* srcA = A + (size_t)bm * DD;
    const __half* srcB = WB + (size_t)bn * DD;

    auto load_stage = [&](int s, int buf) {
        const uint32_t base = su + buf * STG;
        const int k0 = s * 64;
#pragma unroll
        for (int p = 0; p < 6; p++) {
            int idx = p * 256 + tid;
            if (idx < 1024) {
                int row = idx >> 3, col = idx & 7;
                cp16(base + SWZ128(row * 128 + col * 16),
                     srcA + (size_t)row * DD + k0 + col * 8);
            } else {
                int j = idx - 1024;
                int row = j >> 3, col = j & 7;
                cp16(base + 16384 + SWZ128(row * 128 + col * 16),
                     srcB + (size_t)row * DD + k0 + col * 8);
            }
        }
    };

    float c[2][4][4] = {};

    load_stage(0, 0); CP_COMMIT();

    for (int s = 0; s < 8; s++) {
        CP_WAIT(0);
        __syncthreads();
        if (s < 7) { load_stage(s + 1, (s + 1) & 1); CP_COMMIT(); }
        const uint32_t bA = su + (s & 1) * STG;
        const uint32_t bB = bA + 16384;
#pragma unroll
        for (int q = 0; q < 4; q++) {
            uint32_t ah[2][4];
#pragma unroll
            for (int mt = 0; mt < 2; mt++) {
                const int row = wm * 32 + mt * 16 + (lane & 15);
                const uint32_t off = SWZ128(row * 128 + q * 32 + (lane >> 4) * 16);
                LDSM_X4(ah[mt], bA + off);
            }
#pragma unroll
            for (int nt2 = 0; nt2 < 2; nt2++) {
                const int n = wn * 32 + nt2 * 16 + (lane & 7) + ((lane >> 4) & 1) * 8;
                const uint32_t off = SWZ128(n * 128 + q * 32 + ((lane >> 3) & 1) * 16);
                uint32_t bh[4];
                LDSM_X4(bh, bB + off);
#pragma unroll
                for (int mt = 0; mt < 2; mt++) {
                    mma_f16(c[mt][2 * nt2],     ah[mt], bh[0], bh[1]);
                    mma_f16(c[mt][2 * nt2 + 1], ah[mt], bh[2], bh[3]);
                }
            }
        }
    }

#pragma unroll
    for (int mt = 0; mt < 2; mt++) {
        const int r0 = bm + wm * 32 + mt * 16 + (lane >> 2);
#pragma unroll
        for (int nt = 0; nt < 4; nt++) {
            const int n = bn + wn * 32 + nt * 8 + (lane & 3) * 2;
            const float b0v = bias[n], b1v = bias[n + 1];
            float2 p0; p0.x = c[mt][nt][0] + b0v; p0.y = c[mt][nt][1] + b1v;
            float2 p1; p1.x = c[mt][nt][2] + b0v; p1.y = c[mt][nt][3] + b1v;
            *(float2*)(outF + (size_t)r0 * DD + n) = p0;
            *(float2*)(outF + (size_t)(r0 + 8) * DD + n) = p1;
        }
    }
}

// ---------------------------------------------------------------------------
// Local attention (R16 shape + ones-MMA lsum), sliced via bsel + qb_off.
// Q pre-scaled by 0.125*log2e at the source -> p = ex2.approx(S) directly
// (deletes 2 FMULs per exp from the hot loop; MUFU count unchanged).
// ---------------------------------------------------------------------------
__global__ void __launch_bounds__(128, 3) attn_mma(int bsel, int qb_off)
{
    extern __shared__ char smc[];
    const uint32_t su = smem_to_u32(smc);
    const int tid = threadIdx.x, lane = tid & 31, wid = tid >> 5;
    const int bid = blockIdx.x;                // [0, 256)
    const int qb = (bid & 31) + qb_off;
    const int h = bid >> 5;
    const int b = bsel;
    const int qstart = qb * 128;
    const int c = qb >> 1;

    const size_t hb = ((size_t)(b * HH + h)) * TT * DH;
    const __half* Qp = g_Qh + hb;
    const __half* Kp = g_Kh + hb;
    const __half* Vp = g_Vh + hb;

    const int k0 = (c == 0) ? 0 : (c - 1) * WW;
    const int k1 = (c == NC - 1) ? TT : (c + 2) * WW;
    const int ntiles = (k1 - k0) >> 6;

    const uint32_t BUF0 = su;
    const uint32_t QSTG = su + 2 * 16384;

    const uint32_t ONES = 0x3C003C00u;     // half2(1.0, 1.0)

    auto load_kv = [&](int i, int buf) {
        const int kt = k0 + i * 64;
        const uint32_t base = BUF0 + buf * 16384;
#pragma unroll
        for (int p = 0; p < 8; p++) {
            int idx = p * 128 + tid;
            int mtx = idx >> 9, row = (idx >> 3) & 63, col = idx & 7;
            cp16(base + mtx * 8192 + SWZ128(row * 128 + col * 16),
                 (mtx ? Vp : Kp) + (size_t)(kt + row) * DH + col * 8);
        }
    };

#pragma unroll
    for (int p = 0; p < 8; p++) {
        int idx = p * 128 + tid;
        int row = idx >> 3, col = idx & 7;
        cp16(QSTG + SWZ128(row * 128 + col * 16),
             Qp + (size_t)(qstart + row) * DH + col * 8);
    }
    load_kv(0, 0);
    CP_COMMIT();

    float o[2][8][4] = {};
    float ls[2][4] = {};         // ones-MMA accumulators: [0]=row r, [2]=row r+8
    uint32_t qh[2][4][4];

    auto compute = [&](uint32_t kb) {
#pragma unroll
        for (int kt2 = 0; kt2 < 4; kt2++) {
            float sfr[2][2][4] = {};
#pragma unroll
            for (int q = 0; q < 4; q++) {
                const int n = kt2 * 16 + (lane & 7) + ((lane >> 4) & 1) * 8;
                const uint32_t off = SWZ128(n * 128 + q * 32 + ((lane >> 3) & 1) * 16);
                uint32_t kh[4];
                LDSM_X4(kh, kb + off);
#pragma unroll
                for (int mf = 0; mf < 2; mf++) {
                    mma_f16(sfr[mf][0], qh[mf][q], kh[0], kh[1]);
                    mma_f16(sfr[mf][1], qh[mf][q], kh[2], kh[3]);
                }
            }

            // p = rn_fp16(ex2(S')); row sums via ones-MMA on the tensor pipe
            uint32_t ap[2][4];
#pragma unroll
            for (int mf = 0; mf < 2; mf++) {
                float e0 = ex2f(sfr[mf][0][0]);
                float e1 = ex2f(sfr[mf][0][1]);
                float e2 = ex2f(sfr[mf][0][2]);
                float e3 = ex2f(sfr[mf][0][3]);
                float f0 = ex2f(sfr[mf][1][0]);
                float f1 = ex2f(sfr[mf][1][1]);
                float f2 = ex2f(sfr[mf][1][2]);
                float f3 = ex2f(sfr[mf][1][3]);
                ap[mf][0] = pack_h2(e0, e1);
                ap[mf][1] = pack_h2(e2, e3);
                ap[mf][2] = pack_h2(f0, f1);
                ap[mf][3] = pack_h2(f2, f3);
                mma_f16(ls[mf], ap[mf], ONES, ONES);
            }

#pragma unroll
            for (int nt2 = 0; nt2 < 4; nt2++) {
                const int kr = kt2 * 16 + (lane & 7) + ((lane >> 4) & 1) * 8;
                const uint32_t off = SWZ128(kr * 128 + nt2 * 32 + ((lane >> 3) & 1) * 16);
                uint32_t vh[4];
                LDSM_X4T(vh, kb + 8192 + off);
#pragma unroll
                for (int mf = 0; mf < 2; mf++) {
                    mma_f16(o[mf][2 * nt2],     ap[mf], vh[0], vh[2]);
                    mma_f16(o[mf][2 * nt2 + 1], ap[mf], vh[1], vh[3]);
                }
            }
        }
    };

    for (int i = 0; i < ntiles; i++) {
        CP_WAIT(0);
        __syncthreads();
        if (i == 0) {
#pragma unroll
            for (int mf = 0; mf < 2; mf++)
#pragma unroll
                for (int q = 0; q < 4; q++) {
                    const int row = wid * 32 + mf * 16 + (lane & 15);
                    const uint32_t off = SWZ128(row * 128 + q * 32 + (lane >> 4) * 16);
                    LDSM_X4(qh[mf][q], QSTG + off);
                }
        }
        if (i + 1 < ntiles) { load_kv(i + 1, (i + 1) & 1); CP_COMMIT(); }
        compute(BUF0 + (i & 1) * 16384);
    }

    // normalize + store (rn fp16 to [B,T,D]); ls[mf][0]/[2] hold full row sums
#pragma unroll
    for (int mf = 0; mf < 2; mf++) {
        const float inv0 = 1.f / ls[mf][0], inv1 = 1.f / ls[mf][2];

        const int r0 = wid * 32 + mf * 16 + (lane >> 2);
        const int t0g = qstart + r0;
        const size_t o0 = ((size_t)b * TT + t0g) * DD + h * DH + (lane & 3) * 2;
        const size_t o1 = o0 + (size_t)8 * DD;
#pragma unroll
        for (int nt = 0; nt < 8; nt++) {
            *(uint32_t*)(g_Oh + o0 + nt * 8) = pack_h2(o[mf][nt][0] * inv0, o[mf][nt][1] * inv0);
            *(uint32_t*)(g_Oh + o1 + nt * 8) = pack_h2(o[mf][nt][2] * inv1, o[mf][nt][3] * inv1);
        }
    }
}

// ---------------------------------------------------------------------------
// Four-chain pipeline (R14 schedule, best known):
//   qkvA(b) = t [0,4608)   -> attnLo(b) (window <= 4352)  -> projLo(b)
//   qkvB(b) = t [4608,8192) + qkvA(b) -> attnHi(b) (window >= 3840) -> projHi(b)
// ---------------------------------------------------------------------------
extern "C" void kernel_launch(void* const* d_in, const int* in_sizes, int n_in,
                              void* d_out, int out_size)
{
    const float* x  = (const float*)d_in[0];
    const float* Wq = (const float*)d_in[1];
    const float* bq = (const float*)d_in[2];
    const float* Wk = (const float*)d_in[3];
    const float* bk = (const float*)d_in[4];
    const float* Wv = (const float*)d_in[5];
    const float* bv = (const float*)d_in[6];
    const float* Wo = (const float*)d_in[7];
    const float* bo = (const float*)d_in[8];
    float* out = (float*)d_out;

    __half *xh, *Wh, *Qh, *Kh, *Vh, *Oh;
    cudaGetSymbolAddress((void**)&xh, g_xh);
    cudaGetSymbolAddress((void**)&Wh, g_Wh);
    cudaGetSymbolAddress((void**)&Qh, g_Qh);
    cudaGetSymbolAddress((void**)&Kh, g_Kh);
    cudaGetSymbolAddress((void**)&Vh, g_Vh);
    cudaGetSymbolAddress((void**)&Oh, g_Oh);

    const int SMEM_QKV = 81920;            // 2 x 40K
    const int SMEM_P   = 49152;            // 2 x 24K
    const int SMEM_A   = 49152;            // 2 x 16K ring + 16K Q

    static cudaStream_t s1 = nullptr, s2 = nullptr, s3 = nullptr;
    static cudaEvent_t e_conv = nullptr, eA0 = nullptr, eA1 = nullptr;
    static cudaEvent_t j1 = nullptr, j2 = nullptr, j3 = nullptr;
    static bool inited = false;
    if (!inited) {
        cudaFuncSetAttribute(qkv_gemm,  cudaFuncAttributeMaxDynamicSharedMemorySize, SMEM_QKV);
        cudaFuncSetAttribute(proj_gemm, cudaFuncAttributeMaxDynamicSharedMemorySize, SMEM_P);
        cudaFuncSetAttribute(attn_mma,  cudaFuncAttributeMaxDynamicSharedMemorySize, SMEM_A);
        cudaStreamCreateWithFlags(&s1, cudaStreamNonBlocking);
        cudaStreamCreateWithFlags(&s2, cudaStreamNonBlocking);
        cudaStreamCreateWithFlags(&s3, cudaStreamNonBlocking);
        cudaEventCreateWithFlags(&e_conv, cudaEventDisableTiming);
        cudaEventCreateWithFlags(&eA0, cudaEventDisableTiming);
        cudaEventCreateWithFlags(&eA1, cudaEventDisableTiming);
        cudaEventCreateWithFlags(&j1, cudaEventDisableTiming);
        cudaEventCreateWithFlags(&j2, cudaEventDisableTiming);
        cudaEventCreateWithFlags(&j3, cudaEventDisableTiming);
        inited = true;
    }

    // Convert on s0, fork to s1..s3
    const int ntot = NX4 + 4 * NW4;
    convert_inputs<<<(ntot + 255) / 256, 256>>>(
        (const float4*)x, (const float4*)Wq, (const float4*)Wk,
        (const float4*)Wv, (const float4*)Wo);
    cudaEventRecord(e_conv, 0);
    cudaStreamWaitEvent(s1, e_conv, 0);
    cudaStreamWaitEvent(s2, e_conv, 0);
    cudaStreamWaitEvent(s3, e_conv, 0);

    const __half* Wo_h = Wh + (size_t)3 * DD * DD;
    dim3 gA(DD / 64, 36, 1);   // t [0, 4608)
    dim3 gB(DD / 64, 28, 1);   // t [4608, 8192)
    dim3 gP(DD / 64, 32, 1);   // proj half: 4096 rows
    const int ATT_BLKS = HH * 32;

    // s0: qkvA(b0) -> attnLo(b0) -> projLo(b0)
    qkv_gemm<<<gA, 256, SMEM_QKV, 0>>>(xh, Wh, bq, bk, bv, Qh, Kh, Vh, 0);
    cudaEventRecord(eA0, 0);
    attn_mma<<<ATT_BLKS, 128, SMEM_A, 0>>>(0, 0);
    proj_gemm<<<gP, 256, SMEM_P, 0>>>(Oh, Wo_h, bo, out, 0);

    // s1: qkvB(b0); wait qkvA(b0) -> attnHi(b0) -> projHi(b0)
    qkv_gemm<<<gB, 256, SMEM_QKV, s1>>>(xh, Wh, bq, bk, bv, Qh, Kh, Vh, 4608);
    cudaStreamWaitEvent(s1, eA0, 0);
    attn_mma<<<ATT_BLKS, 128, SMEM_A, s1>>>(0, 32);
    proj_gemm<<<gP, 256, SMEM_P, s1>>>(Oh, Wo_h, bo, out, 4096);

    // s2: qkvA(b1) -> attnLo(b1) -> projLo(b1)
    qkv_gemm<<<gA, 256, SMEM_QKV, s2>>>(xh, Wh, bq, bk, bv, Qh, Kh, Vh, TT);
    cudaEventRecord(eA1, s2);
    attn_mma<<<ATT_BLKS, 128, SMEM_A, s2>>>(1, 0);
    proj_gemm<<<gP, 256, SMEM_P, s2>>>(Oh, Wo_h, bo, out, TT);

    // s3: qkvB(b1); wait qkvA(b1) -> attnHi(b1) -> projHi(b1)
    qkv_gemm<<<gB, 256, SMEM_QKV, s3>>>(xh, Wh, bq, bk, bv, Qh, Kh, Vh, TT + 4608);
    cudaStreamWaitEvent(s3, eA1, 0);
    attn_mma<<<ATT_BLKS, 128, SMEM_A, s3>>>(1, 32);
    proj_gemm<<<gP, 256, SMEM_P, s3>>>(Oh, Wo_h, bo, out, TT + 4096);

    // Join all side streams back into s0
    cudaEventRecord(j1, s1);
    cudaEventRecord(j2, s2);
    cudaEventRecord(j3, s3);
    cudaStreamWaitEvent(0, j1, 0);
    cudaStreamWaitEvent(0, j2, 0);
    cudaStreamWaitEvent(0, j3, 0);
}